// round 1
// baseline (speedup 1.0000x reference)
#include <cuda_runtime.h>
#include <cuda_bf16.h>
#include <math.h>

#define NN 15840        // nodes
#define EE 253440       // edges
#define BB 48           // graphs
#define HID 256
#define INCH 128

// ---------------- scratch (static device globals; no allocation) ----------------
__device__ float g_xn[NN * INCH];
__device__ float g_q[NN * HID];
__device__ float g_k[NN * HID];
__device__ float g_v[NN * HID];
__device__ float g_skip[NN * HID];
__device__ float g_alpha[EE];
__device__ float g_m[NN];
__device__ float g_z[NN];
__device__ float g_out[NN * HID];
__device__ float g_bnsum[HID];
__device__ float g_bnsumsq[HID];
__device__ float g_scale[HID];
__device__ float g_shift[HID];
__device__ float g_pool[BB * 18 * HID];
__device__ float g_bacc[BB];

// ---------------- helpers ----------------
__device__ __forceinline__ void atomicMaxF(float* addr, float v) {
    if (v >= 0.f) atomicMax((int*)addr, __float_as_int(v));
    else          atomicMin((unsigned int*)addr, __float_as_uint(v));
}

__device__ __forceinline__ void red_add_v4(float* p, float a, float b, float c, float d) {
    asm volatile("red.global.add.v4.f32 [%0], {%1,%2,%3,%4};"
                 :: "l"(p), "f"(a), "f"(b), "f"(c), "f"(d) : "memory");
}

// ---------------- init scratch ----------------
__global__ void k_init() {
    int i = blockIdx.x * blockDim.x + threadIdx.x;
    int stride = gridDim.x * blockDim.x;
    for (int t = i; t < NN * HID; t += stride) g_out[t] = 0.f;
    for (int t = i; t < NN; t += stride) { g_z[t] = 0.f; g_m[t] = __int_as_float(0xff800000); }
    if (i < HID) { g_bnsum[i] = 0.f; g_bnsumsq[i] = 0.f; }
    if (i < BB) g_bacc[i] = 0.f;
}

// ---------------- LayerNorm over 128 features ----------------
__global__ __launch_bounds__(128) void k_ln(const float* __restrict__ x,
                                            const float* __restrict__ lg,
                                            const float* __restrict__ lb) {
    int row = blockIdx.x;
    int c = threadIdx.x;
    float v = x[row * INCH + c];
    __shared__ float sm[4];
    float s = v;
    #pragma unroll
    for (int o = 16; o; o >>= 1) s += __shfl_xor_sync(~0u, s, o);
    int wid = c >> 5, lane = c & 31;
    if (lane == 0) sm[wid] = s;
    __syncthreads();
    float mean = (sm[0] + sm[1] + sm[2] + sm[3]) * (1.f / 128.f);
    float d = v - mean;
    float s2 = d * d;
    #pragma unroll
    for (int o = 16; o; o >>= 1) s2 += __shfl_xor_sync(~0u, s2, o);
    __syncthreads();
    if (lane == 0) sm[wid] = s2;
    __syncthreads();
    float var = (sm[0] + sm[1] + sm[2] + sm[3]) * (1.f / 128.f);
    g_xn[row * INCH + c] = d * rsqrtf(var + 1e-5f) * lg[c] + lb[c];
}

// ---------------- fused 4-way GEMM: xn[N,128] @ {Wq,Wk,Wv,Wskip}^T + bias ----------------
// out[i][j] = sum_k xn[i][k] * W[j][k] + b[j]; tiles 64x64, K-chunk 32.
__global__ __launch_bounds__(256) void k_gemm(const float* __restrict__ Wq, const float* __restrict__ bq,
                                              const float* __restrict__ Wk, const float* __restrict__ bk,
                                              const float* __restrict__ Wv, const float* __restrict__ bv,
                                              const float* __restrict__ Ws, const float* __restrict__ bs) {
    __shared__ float As[32][65];
    __shared__ float Bs[32][65];
    int cb = blockIdx.x;          // 0..15
    int rb = blockIdx.y;          // 0..247
    int g = (cb * 64) / 256;      // which weight group
    const float* W; const float* bias; float* out;
    if (g == 0)      { W = Wq; bias = bq; out = g_q; }
    else if (g == 1) { W = Wk; bias = bk; out = g_k; }
    else if (g == 2) { W = Wv; bias = bv; out = g_v; }
    else             { W = Ws; bias = bs; out = g_skip; }
    int lc0 = cb * 64 - g * 256;
    int row0 = rb * 64;
    int tx = threadIdx.x & 15, ty = threadIdx.x >> 4;
    float acc[4][4] = {};
    for (int k0 = 0; k0 < 128; k0 += 32) {
        #pragma unroll
        for (int t = threadIdx.x; t < 64 * 32; t += 256) {
            int i = t >> 5, kk = t & 31;
            int r = row0 + i;
            As[kk][i] = (r < NN) ? g_xn[r * INCH + k0 + kk] : 0.f;
        }
        #pragma unroll
        for (int t = threadIdx.x; t < 64 * 32; t += 256) {
            int j = t >> 5, kk = t & 31;
            Bs[kk][j] = W[(lc0 + j) * INCH + k0 + kk];
        }
        __syncthreads();
        #pragma unroll
        for (int kk = 0; kk < 32; kk++) {
            float a[4], b[4];
            #pragma unroll
            for (int r = 0; r < 4; r++) a[r] = As[kk][ty * 4 + r];
            #pragma unroll
            for (int c = 0; c < 4; c++) b[c] = Bs[kk][tx * 4 + c];
            #pragma unroll
            for (int r = 0; r < 4; r++)
                #pragma unroll
                for (int c = 0; c < 4; c++)
                    acc[r][c] += a[r] * b[c];
        }
        __syncthreads();
    }
    #pragma unroll
    for (int r = 0; r < 4; r++) {
        int rr = row0 + ty * 4 + r;
        if (rr >= NN) continue;
        #pragma unroll
        for (int c = 0; c < 4; c++) {
            int cc = lc0 + tx * 4 + c;
            out[rr * HID + cc] = acc[r][c] + bias[cc];
        }
    }
}

// ---------------- pass A: alpha[e] = dot(q[dst], k[src] + We@ea) / 16; segment max ----------------
__global__ __launch_bounds__(256) void k_alpha(const int* __restrict__ ei,
                                               const float* __restrict__ ea,
                                               const float* __restrict__ We) {
    __shared__ float sWe[HID * 5];
    for (int t = threadIdx.x; t < HID * 5; t += 256) sWe[t] = We[t];
    __syncthreads();
    int e = (blockIdx.x * 256 + threadIdx.x) >> 5;
    if (e >= EE) return;
    int lane = threadIdx.x & 31;
    int s = ei[e], d = ei[EE + e];
    float a0 = ea[e * 5 + 0], a1 = ea[e * 5 + 1], a2 = ea[e * 5 + 2],
          a3 = ea[e * 5 + 3], a4 = ea[e * 5 + 4];
    int c0 = lane * 8;
    const float* qr = g_q + (size_t)d * HID + c0;
    const float* kr = g_k + (size_t)s * HID + c0;
    float sum = 0.f;
    #pragma unroll
    for (int u = 0; u < 8; u++) {
        int c = c0 + u;
        float ev = sWe[c * 5 + 0] * a0 + sWe[c * 5 + 1] * a1 + sWe[c * 5 + 2] * a2
                 + sWe[c * 5 + 3] * a3 + sWe[c * 5 + 4] * a4;
        sum += qr[u] * (kr[u] + ev);
    }
    #pragma unroll
    for (int o = 16; o; o >>= 1) sum += __shfl_xor_sync(~0u, sum, o);
    if (lane == 0) {
        float al = sum * 0.0625f;   // / sqrt(256)
        g_alpha[e] = al;
        atomicMaxF(&g_m[d], al);
    }
}

// ---------------- pass B: a = exp(alpha - m[dst]); z[dst] += a ----------------
__global__ __launch_bounds__(256) void k_expz(const int* __restrict__ ei) {
    int e = blockIdx.x * 256 + threadIdx.x;
    if (e >= EE) return;
    int d = ei[EE + e];
    float a = expf(g_alpha[e] - g_m[d]);
    g_alpha[e] = a;
    atomicAdd(&g_z[d], a);
}

// ---------------- pass C: out[dst] += (a/z) * (v[src] + We@ea) ----------------
__global__ __launch_bounds__(256) void k_scatter(const int* __restrict__ ei,
                                                 const float* __restrict__ ea,
                                                 const float* __restrict__ We) {
    __shared__ float sWe[HID * 5];
    for (int t = threadIdx.x; t < HID * 5; t += 256) sWe[t] = We[t];
    __syncthreads();
    int e = (blockIdx.x * 256 + threadIdx.x) >> 5;
    if (e >= EE) return;
    int lane = threadIdx.x & 31;
    int s = ei[e], d = ei[EE + e];
    float w = g_alpha[e] / (g_z[d] + 1e-16f);
    float a0 = ea[e * 5 + 0], a1 = ea[e * 5 + 1], a2 = ea[e * 5 + 2],
          a3 = ea[e * 5 + 3], a4 = ea[e * 5 + 4];
    int c0 = lane * 8;
    const float* vr = g_v + (size_t)s * HID + c0;
    float* orow = g_out + (size_t)d * HID + c0;
    float val[8];
    #pragma unroll
    for (int u = 0; u < 8; u++) {
        int c = c0 + u;
        float ev = sWe[c * 5 + 0] * a0 + sWe[c * 5 + 1] * a1 + sWe[c * 5 + 2] * a2
                 + sWe[c * 5 + 3] * a3 + sWe[c * 5 + 4] * a4;
        val[u] = w * (vr[u] + ev);
    }
    red_add_v4(orow,     val[0], val[1], val[2], val[3]);
    red_add_v4(orow + 4, val[4], val[5], val[6], val[7]);
}

// ---------------- skip add + BN partial stats ----------------
__global__ __launch_bounds__(256) void k_skipbn() {
    int row0 = blockIdx.x * 32;
    int c = threadIdx.x;
    float s1 = 0.f, s2 = 0.f;
    for (int r = 0; r < 32; r++) {
        int row = row0 + r;
        if (row >= NN) break;
        float v = g_out[row * HID + c] + g_skip[row * HID + c];
        g_out[row * HID + c] = v;
        s1 += v; s2 += v * v;
    }
    atomicAdd(&g_bnsum[c], s1);
    atomicAdd(&g_bnsumsq[c], s2);
}

__global__ __launch_bounds__(256) void k_bnfinal(const float* __restrict__ bg,
                                                 const float* __restrict__ bb) {
    int c = threadIdx.x;
    float mean = g_bnsum[c] * (1.f / NN);
    float var = g_bnsumsq[c] * (1.f / NN) - mean * mean;
    float sc = bg[c] * rsqrtf(var + 1e-5f);
    g_scale[c] = sc;
    g_shift[c] = bb[c] - mean * sc;
}

// ---------------- BN apply + ReLU + fused maxpool chain (330 -> 18, window 18) ----------------
__global__ __launch_bounds__(256) void k_pool() {
    int bt = blockIdx.x;          // b*18 + t
    int b = bt / 18, t = bt % 18;
    int c = threadIdx.x;
    float sc = g_scale[c], sh = g_shift[c];
    int base = b * 330 + t * 18;
    float mx = 0.f;               // relu bound
    #pragma unroll
    for (int n = 0; n < 18; n++) {
        float v = g_out[(base + n) * HID + c] * sc + sh;
        mx = fmaxf(mx, v);
    }
    g_pool[bt * HID + c] = mx;
}

// ---------------- head: relu(pool @ W1^T + b1) @ Wr^T, accumulate per graph ----------------
__global__ __launch_bounds__(256) void k_head(const float* __restrict__ W1,
                                              const float* __restrict__ b1,
                                              const float* __restrict__ Wr) {
    __shared__ __align__(16) float row[HID];
    __shared__ float red[8];
    int bt = blockIdx.x;
    int b = bt / 18;
    int tid = threadIdx.x;
    row[tid] = g_pool[bt * HID + tid];
    __syncthreads();
    float acc = b1[tid];
    const float4* w4 = (const float4*)(W1 + tid * HID);
    const float4* r4 = (const float4*)row;
    #pragma unroll 8
    for (int j = 0; j < 64; j++) {
        float4 a = w4[j], r = r4[j];
        acc += a.x * r.x + a.y * r.y + a.z * r.z + a.w * r.w;
    }
    float h = fmaxf(acc, 0.f);
    float p = h * Wr[tid];
    #pragma unroll
    for (int o = 16; o; o >>= 1) p += __shfl_xor_sync(~0u, p, o);
    int wid = tid >> 5, lane = tid & 31;
    if (lane == 0) red[wid] = p;
    __syncthreads();
    if (tid == 0) {
        float tot = 0.f;
        #pragma unroll
        for (int i = 0; i < 8; i++) tot += red[i];
        atomicAdd(&g_bacc[b], tot);
    }
}

__global__ void k_final(const float* __restrict__ br, float* __restrict__ out) {
    int b = threadIdx.x;
    if (b < BB) {
        float c = g_bacc[b] * (1.f / 18.f) + br[0];
        out[b] = 1.f / (1.f + expf(-c));
    }
}

// ---------------- launch ----------------
extern "C" void kernel_launch(void* const* d_in, const int* in_sizes, int n_in,
                              void* d_out, int out_size) {
    const float* x   = (const float*)d_in[0];
    const int*   ei  = (const int*)  d_in[1];
    const float* ea  = (const float*)d_in[2];
    const float* Wq  = (const float*)d_in[4];
    const float* bq  = (const float*)d_in[5];
    const float* Wk  = (const float*)d_in[6];
    const float* bk  = (const float*)d_in[7];
    const float* Wv  = (const float*)d_in[8];
    const float* bv  = (const float*)d_in[9];
    const float* We  = (const float*)d_in[10];
    const float* Wsk = (const float*)d_in[11];
    const float* bsk = (const float*)d_in[12];
    const float* lg  = (const float*)d_in[13];
    const float* lb  = (const float*)d_in[14];
    const float* bg  = (const float*)d_in[15];
    const float* bb  = (const float*)d_in[16];
    const float* W1  = (const float*)d_in[17];
    const float* b1  = (const float*)d_in[18];
    const float* Wr  = (const float*)d_in[19];
    const float* br  = (const float*)d_in[20];
    float* out = (float*)d_out;

    k_init<<<1024, 256>>>();
    k_ln<<<NN, 128>>>(x, lg, lb);
    dim3 gg(16, (NN + 63) / 64);
    k_gemm<<<gg, 256>>>(Wq, bq, Wk, bk, Wv, bv, Wsk, bsk);
    k_alpha<<<EE / 8, 256>>>(ei, ea, We);
    k_expz<<<(EE + 255) / 256, 256>>>(ei);
    k_scatter<<<EE / 8, 256>>>(ei, ea, We);
    k_skipbn<<<(NN + 31) / 32, 256>>>();
    k_bnfinal<<<1, 256>>>(bg, bb);
    k_pool<<<BB * 18, 256>>>();
    k_head<<<BB * 18, 256>>>(W1, b1, Wr);
    k_final<<<1, 64>>>(br, out);
}

// round 2
// speedup vs baseline: 1.7888x; 1.7888x over previous
#include <cuda_runtime.h>
#include <cuda_bf16.h>
#include <math.h>

#define NN 15840        // nodes
#define EE 253440       // edges
#define BB 48           // graphs
#define HID 256
#define INCH 128

// ---------------- scratch ----------------
__device__ float g_xn[NN * INCH];
__device__ float g_q[NN * HID];
__device__ float g_k[NN * HID];
__device__ float g_v[NN * HID];
__device__ float g_skip[NN * HID];
__device__ float g_qwe[NN * 5];
__device__ float g_out[NN * HID];
__device__ int   g_cnt[NN];
__device__ int   g_cur[NN];
__device__ int   g_ofs[NN + 1];
__device__ int   g_ssrc[EE];
__device__ int   g_seid[EE];
__device__ float g_bnsum[HID];
__device__ float g_bnsumsq[HID];
__device__ float g_scale[HID];
__device__ float g_shift[HID];
__device__ float g_pool[BB * 18 * HID];
__device__ float g_bacc[BB];

// ---------------- init ----------------
__global__ void k_init() {
    int i = blockIdx.x * blockDim.x + threadIdx.x;
    int stride = gridDim.x * blockDim.x;
    for (int t = i; t < NN; t += stride) { g_cnt[t] = 0; g_cur[t] = 0; }
    if (i < HID) { g_bnsum[i] = 0.f; g_bnsumsq[i] = 0.f; }
    if (i < BB) g_bacc[i] = 0.f;
}

// ---------------- CSR build ----------------
__global__ __launch_bounds__(256) void k_count(const int* __restrict__ ei) {
    int e = blockIdx.x * 256 + threadIdx.x;
    if (e < EE) atomicAdd(&g_cnt[ei[EE + e]], 1);
}

__global__ __launch_bounds__(1024) void k_scan() {
    __shared__ int warpsum[32];
    int t = threadIdx.x;
    int base = t * 16;
    int loc[16];
    int s = 0;
    #pragma unroll
    for (int i = 0; i < 16; i++) {
        int idx = base + i;
        int c = (idx < NN) ? g_cnt[idx] : 0;
        loc[i] = s; s += c;
    }
    int lane = t & 31, wid = t >> 5;
    int v = s;
    #pragma unroll
    for (int o = 1; o < 32; o <<= 1) {
        int n = __shfl_up_sync(~0u, v, o);
        if (lane >= o) v += n;
    }
    if (lane == 31) warpsum[wid] = v;
    __syncthreads();
    if (wid == 0) {
        int w = warpsum[lane];
        #pragma unroll
        for (int o = 1; o < 32; o <<= 1) {
            int n = __shfl_up_sync(~0u, w, o);
            if (lane >= o) w += n;
        }
        warpsum[lane] = w;
    }
    __syncthreads();
    int offset = (v - s) + (wid ? warpsum[wid - 1] : 0);
    #pragma unroll
    for (int i = 0; i < 16; i++) {
        int idx = base + i;
        if (idx < NN) g_ofs[idx] = offset + loc[i];
    }
    if (t == 1023) g_ofs[NN] = offset + s;
}

__global__ __launch_bounds__(256) void k_fill(const int* __restrict__ ei) {
    int e = blockIdx.x * 256 + threadIdx.x;
    if (e >= EE) return;
    int d = ei[EE + e];
    int pos = atomicAdd(&g_cur[d], 1);
    int slot = g_ofs[d] + pos;
    g_ssrc[slot] = ei[e];
    g_seid[slot] = e;
}

// ---------------- LayerNorm over 128 features ----------------
__global__ __launch_bounds__(128) void k_ln(const float* __restrict__ x,
                                            const float* __restrict__ lg,
                                            const float* __restrict__ lb) {
    int row = blockIdx.x;
    int c = threadIdx.x;
    float v = x[row * INCH + c];
    __shared__ float sm[4];
    float s = v;
    #pragma unroll
    for (int o = 16; o; o >>= 1) s += __shfl_xor_sync(~0u, s, o);
    int wid = c >> 5, lane = c & 31;
    if (lane == 0) sm[wid] = s;
    __syncthreads();
    float mean = (sm[0] + sm[1] + sm[2] + sm[3]) * (1.f / 128.f);
    float d = v - mean;
    float s2 = d * d;
    #pragma unroll
    for (int o = 16; o; o >>= 1) s2 += __shfl_xor_sync(~0u, s2, o);
    __syncthreads();
    if (lane == 0) sm[wid] = s2;
    __syncthreads();
    float var = (sm[0] + sm[1] + sm[2] + sm[3]) * (1.f / 128.f);
    g_xn[row * INCH + c] = d * rsqrtf(var + 1e-5f) * lg[c] + lb[c];
}

// ---------------- fused 4-way GEMM ----------------
__global__ __launch_bounds__(256) void k_gemm(const float* __restrict__ Wq, const float* __restrict__ bq,
                                              const float* __restrict__ Wk, const float* __restrict__ bk,
                                              const float* __restrict__ Wv, const float* __restrict__ bv,
                                              const float* __restrict__ Ws, const float* __restrict__ bs) {
    __shared__ float As[32][65];
    __shared__ float Bs[32][65];
    int cb = blockIdx.x;
    int rb = blockIdx.y;
    int g = (cb * 64) / 256;
    const float* W; const float* bias; float* out;
    if (g == 0)      { W = Wq; bias = bq; out = g_q; }
    else if (g == 1) { W = Wk; bias = bk; out = g_k; }
    else if (g == 2) { W = Wv; bias = bv; out = g_v; }
    else             { W = Ws; bias = bs; out = g_skip; }
    int lc0 = cb * 64 - g * 256;
    int row0 = rb * 64;
    int tx = threadIdx.x & 15, ty = threadIdx.x >> 4;
    float acc[4][4] = {};
    for (int k0 = 0; k0 < 128; k0 += 32) {
        #pragma unroll
        for (int t = threadIdx.x; t < 64 * 32; t += 256) {
            int i = t >> 5, kk = t & 31;
            int r = row0 + i;
            As[kk][i] = (r < NN) ? g_xn[r * INCH + k0 + kk] : 0.f;
        }
        #pragma unroll
        for (int t = threadIdx.x; t < 64 * 32; t += 256) {
            int j = t >> 5, kk = t & 31;
            Bs[kk][j] = W[(lc0 + j) * INCH + k0 + kk];
        }
        __syncthreads();
        #pragma unroll
        for (int kk = 0; kk < 32; kk++) {
            float a[4], b[4];
            #pragma unroll
            for (int r = 0; r < 4; r++) a[r] = As[kk][ty * 4 + r];
            #pragma unroll
            for (int c = 0; c < 4; c++) b[c] = Bs[kk][tx * 4 + c];
            #pragma unroll
            for (int r = 0; r < 4; r++)
                #pragma unroll
                for (int c = 0; c < 4; c++)
                    acc[r][c] += a[r] * b[c];
        }
        __syncthreads();
    }
    #pragma unroll
    for (int r = 0; r < 4; r++) {
        int rr = row0 + ty * 4 + r;
        if (rr >= NN) continue;
        #pragma unroll
        for (int c = 0; c < 4; c++) {
            int cc = lc0 + tx * 4 + c;
            out[rr * HID + cc] = acc[r][c] + bias[cc];
        }
    }
}

// ---------------- qWe[n][j] = sum_c q[n][c] * We[c][j] ----------------
__global__ __launch_bounds__(256) void k_qwe(const float* __restrict__ We) {
    __shared__ float sWe[HID * 5];
    for (int t = threadIdx.x; t < HID * 5; t += 256) sWe[t] = We[t];
    __syncthreads();
    int node = blockIdx.x * 8 + (threadIdx.x >> 5);
    if (node >= NN) return;
    int lane = threadIdx.x & 31;
    int c0 = lane * 8;
    float q[8];
    #pragma unroll
    for (int u = 0; u < 8; u++) q[u] = g_q[node * HID + c0 + u];
    float p[5] = {};
    #pragma unroll
    for (int u = 0; u < 8; u++) {
        int c = c0 + u;
        #pragma unroll
        for (int j = 0; j < 5; j++) p[j] += q[u] * sWe[c * 5 + j];
    }
    #pragma unroll
    for (int j = 0; j < 5; j++) {
        #pragma unroll
        for (int o = 16; o; o >>= 1) p[j] += __shfl_xor_sync(~0u, p[j], o);
    }
    if (lane < 5) g_qwe[node * 5 + lane] = p[lane];
}

// ---------------- fused attention: online softmax gather per node ----------------
__global__ __launch_bounds__(256) void k_agg(const float* __restrict__ ea,
                                             const float* __restrict__ We) {
    __shared__ float sWe[HID * 5];
    for (int t = threadIdx.x; t < HID * 5; t += 256) sWe[t] = We[t];
    __syncthreads();
    int node = blockIdx.x * 8 + (threadIdx.x >> 5);
    if (node >= NN) return;
    int lane = threadIdx.x & 31;
    int c0 = lane * 8;
    int beg = g_ofs[node], end = g_ofs[node + 1];

    const float4* qp = (const float4*)(g_q + (size_t)node * HID + c0);
    float4 q0 = qp[0], q1 = qp[1];
    float qw0 = g_qwe[node * 5 + 0], qw1 = g_qwe[node * 5 + 1], qw2 = g_qwe[node * 5 + 2],
          qw3 = g_qwe[node * 5 + 3], qw4 = g_qwe[node * 5 + 4];

    float m = -__int_as_float(0x7f800000) * 0.f - 1e30f;  // large negative
    m = -1e30f;
    float z = 0.f;
    float acc[8] = {};
    float ae0 = 0.f, ae1 = 0.f, ae2 = 0.f, ae3 = 0.f, ae4 = 0.f;

    for (int a = beg; a < end; a++) {
        int s = g_ssrc[a];
        int eid = g_seid[a];
        const float* eap = ea + (size_t)eid * 5;
        float e0 = eap[0], e1 = eap[1], e2 = eap[2], e3 = eap[3], e4 = eap[4];
        const float4* kp = (const float4*)(g_k + (size_t)s * HID + c0);
        float4 k0 = kp[0], k1 = kp[1];
        const float4* vp = (const float4*)(g_v + (size_t)s * HID + c0);
        float4 v0 = vp[0], v1 = vp[1];

        float dot = q0.x * k0.x + q0.y * k0.y + q0.z * k0.z + q0.w * k0.w
                  + q1.x * k1.x + q1.y * k1.y + q1.z * k1.z + q1.w * k1.w;
        #pragma unroll
        for (int o = 16; o; o >>= 1) dot += __shfl_xor_sync(~0u, dot, o);
        float alpha = (dot + qw0 * e0 + qw1 * e1 + qw2 * e2 + qw3 * e3 + qw4 * e4) * 0.0625f;

        float nm = fmaxf(m, alpha);
        float sc = __expf(m - nm);
        float w  = __expf(alpha - nm);
        m = nm;
        z = z * sc + w;
        acc[0] = acc[0] * sc + w * v0.x;
        acc[1] = acc[1] * sc + w * v0.y;
        acc[2] = acc[2] * sc + w * v0.z;
        acc[3] = acc[3] * sc + w * v0.w;
        acc[4] = acc[4] * sc + w * v1.x;
        acc[5] = acc[5] * sc + w * v1.y;
        acc[6] = acc[6] * sc + w * v1.z;
        acc[7] = acc[7] * sc + w * v1.w;
        ae0 = ae0 * sc + w * e0;
        ae1 = ae1 * sc + w * e1;
        ae2 = ae2 * sc + w * e2;
        ae3 = ae3 * sc + w * e3;
        ae4 = ae4 * sc + w * e4;
    }

    float inv = 1.f / (z + 1e-16f);
    const float* skp = g_skip + (size_t)node * HID + c0;
    float* op = g_out + (size_t)node * HID + c0;
    #pragma unroll
    for (int u = 0; u < 8; u++) {
        int c = c0 + u;
        float ev = sWe[c * 5 + 0] * ae0 + sWe[c * 5 + 1] * ae1 + sWe[c * 5 + 2] * ae2
                 + sWe[c * 5 + 3] * ae3 + sWe[c * 5 + 4] * ae4;
        op[u] = (acc[u] + ev) * inv + skp[u];
    }
}

// ---------------- BN stats ----------------
__global__ __launch_bounds__(256) void k_bnstat() {
    int row0 = blockIdx.x * 32;
    int c = threadIdx.x;
    float s1 = 0.f, s2 = 0.f;
    for (int r = 0; r < 32; r++) {
        int row = row0 + r;
        if (row >= NN) break;
        float v = g_out[row * HID + c];
        s1 += v; s2 += v * v;
    }
    atomicAdd(&g_bnsum[c], s1);
    atomicAdd(&g_bnsumsq[c], s2);
}

__global__ __launch_bounds__(256) void k_bnfinal(const float* __restrict__ bg,
                                                 const float* __restrict__ bb) {
    int c = threadIdx.x;
    float mean = g_bnsum[c] * (1.f / NN);
    float var = g_bnsumsq[c] * (1.f / NN) - mean * mean;
    float sc = bg[c] * rsqrtf(var + 1e-5f);
    g_scale[c] = sc;
    g_shift[c] = bb[c] - mean * sc;
}

// ---------------- BN apply + ReLU + fused maxpool (330 -> 18) ----------------
__global__ __launch_bounds__(256) void k_pool() {
    int bt = blockIdx.x;
    int b = bt / 18, t = bt % 18;
    int c = threadIdx.x;
    float sc = g_scale[c], sh = g_shift[c];
    int base = b * 330 + t * 18;
    float mx = 0.f;
    #pragma unroll
    for (int n = 0; n < 18; n++) {
        float v = g_out[(base + n) * HID + c] * sc + sh;
        mx = fmaxf(mx, v);
    }
    g_pool[bt * HID + c] = mx;
}

// ---------------- head ----------------
__global__ __launch_bounds__(256) void k_head(const float* __restrict__ W1,
                                              const float* __restrict__ b1,
                                              const float* __restrict__ Wr) {
    __shared__ __align__(16) float row[HID];
    __shared__ float red[8];
    int bt = blockIdx.x;
    int b = bt / 18;
    int tid = threadIdx.x;
    row[tid] = g_pool[bt * HID + tid];
    __syncthreads();
    float acc = b1[tid];
    const float4* w4 = (const float4*)(W1 + tid * HID);
    const float4* r4 = (const float4*)row;
    #pragma unroll 8
    for (int j = 0; j < 64; j++) {
        float4 a = w4[j], r = r4[j];
        acc += a.x * r.x + a.y * r.y + a.z * r.z + a.w * r.w;
    }
    float h = fmaxf(acc, 0.f);
    float p = h * Wr[tid];
    #pragma unroll
    for (int o = 16; o; o >>= 1) p += __shfl_xor_sync(~0u, p, o);
    int wid = tid >> 5, lane = tid & 31;
    if (lane == 0) red[wid] = p;
    __syncthreads();
    if (tid == 0) {
        float tot = 0.f;
        #pragma unroll
        for (int i = 0; i < 8; i++) tot += red[i];
        atomicAdd(&g_bacc[b], tot);
    }
}

__global__ void k_final(const float* __restrict__ br, float* __restrict__ out) {
    int b = threadIdx.x;
    if (b < BB) {
        float c = g_bacc[b] * (1.f / 18.f) + br[0];
        out[b] = 1.f / (1.f + expf(-c));
    }
}

// ---------------- launch ----------------
extern "C" void kernel_launch(void* const* d_in, const int* in_sizes, int n_in,
                              void* d_out, int out_size) {
    const float* x   = (const float*)d_in[0];
    const int*   ei  = (const int*)  d_in[1];
    const float* ea  = (const float*)d_in[2];
    const float* Wq  = (const float*)d_in[4];
    const float* bq  = (const float*)d_in[5];
    const float* Wk  = (const float*)d_in[6];
    const float* bk  = (const float*)d_in[7];
    const float* Wv  = (const float*)d_in[8];
    const float* bv  = (const float*)d_in[9];
    const float* We  = (const float*)d_in[10];
    const float* Wsk = (const float*)d_in[11];
    const float* bsk = (const float*)d_in[12];
    const float* lg  = (const float*)d_in[13];
    const float* lb  = (const float*)d_in[14];
    const float* bg  = (const float*)d_in[15];
    const float* bb  = (const float*)d_in[16];
    const float* W1  = (const float*)d_in[17];
    const float* b1  = (const float*)d_in[18];
    const float* Wr  = (const float*)d_in[19];
    const float* br  = (const float*)d_in[20];
    float* out = (float*)d_out;

    k_init<<<128, 256>>>();
    k_count<<<(EE + 255) / 256, 256>>>(ei);
    k_scan<<<1, 1024>>>();
    k_fill<<<(EE + 255) / 256, 256>>>(ei);
    k_ln<<<NN, 128>>>(x, lg, lb);
    dim3 gg(16, (NN + 63) / 64);
    k_gemm<<<gg, 256>>>(Wq, bq, Wk, bk, Wv, bv, Wsk, bsk);
    k_qwe<<<(NN + 7) / 8, 256>>>(We);
    k_agg<<<(NN + 7) / 8, 256>>>(ea, We);
    k_bnstat<<<(NN + 31) / 32, 256>>>();
    k_bnfinal<<<1, 256>>>(bg, bb);
    k_pool<<<BB * 18, 256>>>();
    k_head<<<BB * 18, 256>>>(W1, b1, Wr);
    k_final<<<1, 64>>>(br, out);
}